// round 7
// baseline (speedup 1.0000x reference)
#include <cuda_runtime.h>
#include <cuda_bf16.h>
#include <cstdint>

#define BATCH 4
#define NC 32
#define CIN 224
#define VOL 32768
#define KT 16512

__device__ float  g_state[BATCH * NC * VOL];
__device__ float  g_feat [BATCH * CIN * VOL];
__device__ double g_sumd [BATCH * CIN];
__device__ double g_sqd  [BATCH * CIN];
__device__ float  g_zn   [BATCH];
__device__ float  g_theta[BATCH * KT];
__device__ float  g_w    [BATCH * KT];
__device__ __align__(16) char g_wb[BATCH * 65536];  // bf16 hi/lo B images

// offsets (floats) inside per-batch g_w block
#define WC_OFF  0       // [224][64]: 0..31 = W_in', 32..63 = W_sh'
#define B64_OFF 14336
#define WM_OFF  14400
#define BM_OFF  15424
#define WO_OFF  15456
#define BO_OFF  16480

#define FMA2(acc, w, x) asm("fma.rn.f32x2 %0, %1, %2, %0;" : "+l"(acc) : "l"(w), "l"(x))
#define BCAST(d, f)     asm("mov.b64 %0, {%1, %1};" : "=l"(d) : "f"(f))
#define UNPK(lo, hi, q) asm("mov.b64 {%0, %1}, %2;" : "=f"(lo), "=f"(hi) : "l"(q))
#define CPA16(dst, src) asm volatile("cp.async.cg.shared.global [%0], [%1], 16;" :: "r"(dst), "l"(src))
#define CPCOMMIT()      asm volatile("cp.async.commit_group;")
#define CPWAIT(n)       asm volatile("cp.async.wait_group %0;" :: "n"(n))

#define MMA_BF16(c, a0, a1, a2, a3, b0, b1) \
    asm("mma.sync.aligned.m16n8k16.row.col.f32.bf16.bf16.f32 " \
        "{%0,%1,%2,%3}, {%4,%5,%6,%7}, {%8,%9}, {%0,%1,%2,%3};" \
        : "+f"((c)[0]), "+f"((c)[1]), "+f"((c)[2]), "+f"((c)[3]) \
        : "r"(a0), "r"(a1), "r"(a2), "r"(a3), "r"(b0), "r"(b1))

// ---------------- setup ----------------

__global__ void k_norm(const float* __restrict__ z) {
    int b = blockIdx.x, t = threadIdx.x;
    float v0 = z[b * 512 + t], v1 = z[b * 512 + 256 + t];
    float s = v0 * v0 + v1 * v1;
    #pragma unroll
    for (int o = 16; o; o >>= 1) s += __shfl_down_sync(~0u, s, o);
    __shared__ float sh[8];
    if ((t & 31) == 0) sh[t >> 5] = s;
    __syncthreads();
    if (t < 8) {
        float x = sh[t];
        #pragma unroll
        for (int o = 4; o; o >>= 1) x += __shfl_down_sync(0xffu, x, o);
        if (t == 0) g_zn[b] = fmaxf(sqrtf(x), 1e-12f);
    }
}

__global__ void k_init(const float* __restrict__ z) {
    int b = blockIdx.y;
    int v = (blockIdx.x << 8) + threadIdx.x;
    float val = 0.f;
    if (v < 512) val = z[b * 512 + v] / g_zn[b];
    #pragma unroll
    for (int c = 0; c < NC; c++) g_state[((b * NC + c) << 15) + v] = val;
}

__global__ void k_theta(const int* __restrict__ y, const float* __restrict__ hw,
                        const float* __restrict__ hb) {
    int i = blockIdx.x * 256 + threadIdx.x;
    if (i >= BATCH * KT) return;
    int b = i / KT, k = i - b * KT;
    g_theta[i] = hw[y[b] * KT + k] + hb[k];
}

// ---------------- sobel (unchanged) ----------------

__global__ void __launch_bounds__(512) k_sobel() {
    __shared__ float sl[2][4][36][32];
    __shared__ float red[16][14];
    const int c = blockIdx.x, b = blockIdx.y;
    const int tid = threadIdx.x;
    const int lane = tid & 31, wid = tid >> 5;
    const int h0 = wid * 2;
    const float* __restrict__ xin = g_state + ((size_t)(b * NC + c) << 15);
    float* __restrict__ featb = g_feat + (size_t)(b * CIN + c) * VOL;

    for (int i = tid; i < 1024; i += 512) {
        int w = i & 31, r = (i >> 5) & 3, arr = (i >> 7) & 3, bu = i >> 9;
        int hp = (r < 2) ? r : r + 32;
        sl[bu][arr][hp][w] = 0.f;
    }

    const float R2 = 0.70710678118654752f;
    const float S1 = 1.f + R2;

    float stat[14];
    #pragma unroll
    for (int i = 0; i < 14; i++) stat[i] = 0.f;
    float W[2][6][5];
    #pragma unroll
    for (int r = 0; r < 2; r++)
        #pragma unroll
        for (int a = 0; a < 6; a++)
            #pragma unroll
            for (int k = 0; k < 5; k++) W[r][a][k] = 0.f;

    float xc[2];
    xc[0] = xin[((h0 + 0) << 5) + lane];
    xc[1] = xin[((h0 + 1) << 5) + lane];

    __syncthreads();

    float sw3[2], dw3[2], sw5[2], dw5[2];

    #pragma unroll 2
    for (int s = 0; s < 34; s++) {
        const int bu = s & 1;
        float xn0 = 0.f, xn1 = 0.f;
        if (s + 1 < 32) {
            xn0 = xin[((s + 1) << 10) + ((h0 + 0) << 5) + lane];
            xn1 = xin[((s + 1) << 10) + ((h0 + 1) << 5) + lane];
        }
        if (s < 32) {
            #pragma unroll
            for (int r = 0; r < 2; r++) {
                float xv = xc[r];
                stat[0] += xv; stat[1] += xv * xv;
                float xm1 = __shfl_up_sync(~0u, xv, 1);   if (lane == 0)  xm1 = 0.f;
                float xm2 = __shfl_up_sync(~0u, xv, 2);   if (lane < 2)   xm2 = 0.f;
                float xp1 = __shfl_down_sync(~0u, xv, 1); if (lane == 31) xp1 = 0.f;
                float xp2 = __shfl_down_sync(~0u, xv, 2); if (lane > 29)  xp2 = 0.f;
                sw3[r] = xm1 + 2.f * xv + xp1;
                dw3[r] = xp1 - xm1;
                sw5[r] = xm2 + xp2 + S1 * (xm1 + xp1) + 2.f * xv;
                dw5[r] = (xp2 - xm2) + R2 * (xp1 - xm1);
                int hp = h0 + r + 2;
                sl[bu][0][hp][lane] = sw3[r];
                sl[bu][1][hp][lane] = dw3[r];
                sl[bu][2][hp][lane] = sw5[r];
                sl[bu][3][hp][lane] = dw5[r];
            }
        }
        xc[0] = xn0; xc[1] = xn1;
        __syncthreads();
        #pragma unroll
        for (int r = 0; r < 2; r++) {
            float a30, a31, a32, a50, a51, a52;
            if (s < 32) {
                int hp = h0 + r + 2;
                float s3m = sl[bu][0][hp - 1][lane], s3p = sl[bu][0][hp + 1][lane];
                float d3m = sl[bu][1][hp - 1][lane], d3p = sl[bu][1][hp + 1][lane];
                float s5m2 = sl[bu][2][hp - 2][lane], s5m1 = sl[bu][2][hp - 1][lane];
                float s5p1 = sl[bu][2][hp + 1][lane], s5p2 = sl[bu][2][hp + 2][lane];
                float d5m2 = sl[bu][3][hp - 2][lane], d5m1 = sl[bu][3][hp - 1][lane];
                float d5p1 = sl[bu][3][hp + 1][lane], d5p2 = sl[bu][3][hp + 2][lane];
                a30 = d3m + 2.f * dw3[r] + d3p;
                a31 = s3p - s3m;
                a32 = s3m + 2.f * sw3[r] + s3p;
                a50 = d5m2 + d5p2 + S1 * (d5m1 + d5p1) + 2.f * dw5[r];
                a51 = (s5p2 - s5m2) + R2 * (s5p1 - s5m1);
                a52 = s5m2 + s5p2 + S1 * (s5m1 + s5p1) + 2.f * sw5[r];
            } else {
                a30 = a31 = a32 = a50 = a51 = a52 = 0.f;
            }
            #pragma unroll
            for (int a = 0; a < 6; a++) {
                W[r][a][0] = W[r][a][1]; W[r][a][1] = W[r][a][2];
                W[r][a][2] = W[r][a][3]; W[r][a][3] = W[r][a][4];
            }
            W[r][0][4] = a32; W[r][1][4] = a31; W[r][2][4] = a30;
            W[r][3][4] = a52; W[r][4][4] = a51; W[r][5][4] = a50;

            if (s >= 2) {
                int dc = s - 2;
                float o1 = W[r][0][3] - W[r][0][1];
                float o2 = W[r][1][1] + 2.f * W[r][1][2] + W[r][1][3];
                float o3 = W[r][2][1] + 2.f * W[r][2][2] + W[r][2][3];
                float o4 = (W[r][3][4] - W[r][3][0]) + R2 * (W[r][3][3] - W[r][3][1]);
                float o5 = W[r][4][0] + W[r][4][4] + S1 * (W[r][4][1] + W[r][4][3]) + 2.f * W[r][4][2];
                float o6 = W[r][5][0] + W[r][5][4] + S1 * (W[r][5][1] + W[r][5][3]) + 2.f * W[r][5][2];
                int v = (dc << 10) + ((h0 + r) << 5) + lane;
                featb[(size_t)32 * VOL + v]  = o1;
                featb[(size_t)64 * VOL + v]  = o2;
                featb[(size_t)96 * VOL + v]  = o3;
                featb[(size_t)128 * VOL + v] = o4;
                featb[(size_t)160 * VOL + v] = o5;
                featb[(size_t)192 * VOL + v] = o6;
                stat[2]  += o1; stat[3]  += o1 * o1;
                stat[4]  += o2; stat[5]  += o2 * o2;
                stat[6]  += o3; stat[7]  += o3 * o3;
                stat[8]  += o4; stat[9]  += o4 * o4;
                stat[10] += o5; stat[11] += o5 * o5;
                stat[12] += o6; stat[13] += o6 * o6;
            }
        }
    }

    #pragma unroll
    for (int i = 0; i < 14; i++) {
        float v = stat[i];
        #pragma unroll
        for (int o = 16; o; o >>= 1) v += __shfl_down_sync(~0u, v, o);
        stat[i] = v;
    }
    if (lane == 0)
        #pragma unroll
        for (int i = 0; i < 14; i++) red[wid][i] = stat[i];
    __syncthreads();
    if (tid < 14) {
        double acc = 0.0;
        #pragma unroll
        for (int k = 0; k < 16; k++) acc += (double)red[k][tid];
        int g = tid >> 1;
        if (tid & 1) g_sqd [b * CIN + g * 32 + c] = acc;
        else         g_sumd[b * CIN + g * 32 + c] = acc;
    }
}

// ------- fold norm into weights + build bf16 hi/lo B images -------
// B image per chunk kc (14): Bh[64 n][16 k] bf16, 36B row pitch (2304B),
// then Bl (2304B). chunk block = 4608B.

__global__ void k_fold() {
    int b = blockIdx.x, tid = threadIdx.x;
    int lane = tid & 31, wid = tid >> 5;
    __shared__ float smean[CIN], srs[CIN];
    if (tid < CIN) {
        double m = g_sumd[b * CIN + tid] * (1.0 / 32768.0);
        double var = g_sqd[b * CIN + tid] * (1.0 / 32768.0) - m * m;
        smean[tid] = (float)m;
        srs[tid] = (float)rsqrt(var + 1e-5);
    }
    __syncthreads();
    const float* th = g_theta + b * KT;
    float* w = g_w + b * KT;
    #pragma unroll
    for (int j = 0; j < 8; j++) {
        int o = wid * 8 + j;
        int off = (o < 32) ? o * 224 : 9312 + (o - 32) * 224;
        float corr = 0.f;
        #pragma unroll
        for (int q = 0; q < 7; q++) {
            int cc = lane + q * 32;
            float wv = th[off + cc] * srs[cc];
            w[WC_OFF + cc * 64 + o] = wv;
            corr += wv * smean[cc];
        }
        #pragma unroll
        for (int d = 16; d; d >>= 1) corr += __shfl_down_sync(~0u, corr, d);
        if (lane == 0) {
            float braw = (o < 32) ? th[7168 + o] : th[16480 + o - 32];
            w[B64_OFF + o] = braw - corr;
        }
    }
    for (int i = tid; i < 1024; i += 256) {
        int r = i >> 5, cc = i & 31;
        w[WM_OFF + cc * 32 + r] = th[7200 + r * 32 + cc];
        w[WO_OFF + cc * 32 + r] = th[8256 + r * 32 + cc];
    }
    if (tid < 32) {
        w[BM_OFF + tid] = th[8224 + tid];
        w[BO_OFF + tid] = th[9280 + tid];
    }
    __syncthreads();
    char* wbb = g_wb + b * 65536;
    for (int i = tid; i < 14336; i += 256) {
        int kc = i >> 10, rem = i & 1023, n = rem >> 4, kk = rem & 15;
        int r = kc * 16 + kk;
        float val = w[WC_OFF + r * 64 + n];
        __nv_bfloat16 bh = __float2bfloat16(val);
        __nv_bfloat16 bl = __float2bfloat16(val - __bfloat162float(bh));
        *(__nv_bfloat16*)(wbb + kc * 4608 + n * 36 + kk * 2) = bh;
        *(__nv_bfloat16*)(wbb + kc * 4608 + 2304 + n * 36 + kk * 2) = bl;
    }
}

// ---------------- mma.sync residual MLP ----------------
// block: 128 vox (M) x 64 out (N), K=224 in 14 k16 chunks.
// smem (bytes): A ring [2][Ah 4608 | Al 4608] at 0..18432
//               B ring [2][Bh+Bl 4608]       at 18432..27648
//   union with HSO floats [64][132] = 33792B
// SWB floats at 8448 (2176 floats), H2S floats at 10624 ([32][129])
#define SWB_F 8448
#define H2S_F 10624
#define RES_SMEM 59008

__global__ void __launch_bounds__(256) k_residual() {
    extern __shared__ __align__(16) char smb[];
    float* smf = (float*)smb;
    const int tid = threadIdx.x;
    const int w = tid >> 5, lane = tid & 31;
    const int g = lane >> 2, t = lane & 3;
    const int b = blockIdx.y;
    const int v0 = blockIdx.x << 7;
    const float* gw = g_w + b * KT;
    uint32_t swa;
    asm("{ .reg .u64 tt; cvta.to.shared.u64 tt, %1; cvt.u32.u64 %0, tt; }"
        : "=r"(swa) : "l"(smb));

    // stage-2 weights -> smem (region disjoint from A/B buffers)
    if (tid < 64)  smf[SWB_F + tid]      = gw[B64_OFF + tid];
    if (tid < 32)  smf[SWB_F + 64 + tid] = gw[BM_OFF + tid];
    if (tid >= 32 && tid < 64) smf[SWB_F + 96 + (tid - 32)] = gw[BO_OFF + tid - 32];
    for (int i = tid; i < 1024; i += 256) smf[SWB_F + 128 + i]  = gw[WM_OFF + i];
    for (int i = tid; i < 1024; i += 256) smf[SWB_F + 1152 + i] = gw[WO_OFF + i];

    auto xptr = [&](int r) -> const float* {
        return ((r < 32) ? g_state + ((size_t)(b * NC + r) << 15)
                         : g_feat  + ((size_t)(b * CIN + r) << 15)) + v0;
    };
    // convert 16 channels of x into Ah/Al bf16 (row pitch 36B)
    const int k2 = (tid & 7) * 2, mg = tid >> 3;
    auto convA = [&](int kc) {
        char* ab = smb + (kc & 1) * 9216;
        int r = kc * 16 + k2;
        float4 u = *(const float4*)(xptr(r) + mg * 4);
        float4 vv = *(const float4*)(xptr(r + 1) + mg * 4);
        float ue[4] = {u.x, u.y, u.z, u.w};
        float ve[4] = {vv.x, vv.y, vv.z, vv.w};
        #pragma unroll
        for (int i = 0; i < 4; i++) {
            int m = mg * 4 + i;
            __nv_bfloat162 hh, ll;
            hh.x = __float2bfloat16(ue[i]);
            hh.y = __float2bfloat16(ve[i]);
            ll.x = __float2bfloat16(ue[i] - __bfloat162float(hh.x));
            ll.y = __float2bfloat16(ve[i] - __bfloat162float(hh.y));
            *(uint32_t*)(ab + m * 36 + k2 * 2)        = *(uint32_t*)&hh;
            *(uint32_t*)(ab + 4608 + m * 36 + k2 * 2) = *(uint32_t*)&ll;
        }
    };
    auto cpB = [&](int kc) {
        const char* src = g_wb + b * 65536 + kc * 4608;
        uint32_t dst = swa + 18432 + (kc & 1) * 4608;
        CPA16(dst + tid * 16, src + tid * 16);
        if (tid < 32) CPA16(dst + 4096 + tid * 16, src + 4096 + tid * 16);
    };

    cpB(0); CPCOMMIT();
    convA(0);

    float acc[8][4];
    #pragma unroll
    for (int nt = 0; nt < 8; nt++)
        #pragma unroll
        for (int e = 0; e < 4; e++) acc[nt][e] = 0.f;

    for (int kc = 0; kc < 14; kc++) {
        CPWAIT(0);
        __syncthreads();
        if (kc + 1 < 14) { cpB(kc + 1); CPCOMMIT(); convA(kc + 1); }
        const char* ab = smb + (kc & 1) * 9216;
        const char* bb = smb + 18432 + (kc & 1) * 4608;
        const char* arow = ab + (w * 16 + g) * 36 + t * 4;
        uint32_t ah0 = *(const uint32_t*)(arow);
        uint32_t ah1 = *(const uint32_t*)(arow + 8 * 36);
        uint32_t ah2 = *(const uint32_t*)(arow + 16);
        uint32_t ah3 = *(const uint32_t*)(arow + 8 * 36 + 16);
        uint32_t al0 = *(const uint32_t*)(arow + 4608);
        uint32_t al1 = *(const uint32_t*)(arow + 4608 + 8 * 36);
        uint32_t al2 = *(const uint32_t*)(arow + 4608 + 16);
        uint32_t al3 = *(const uint32_t*)(arow + 4608 + 8 * 36 + 16);
        #pragma unroll
        for (int nt = 0; nt < 8; nt++) {
            const char* brow = bb + (nt * 8 + g) * 36 + t * 4;
            uint32_t bh0 = *(const uint32_t*)(brow);
            uint32_t bh1 = *(const uint32_t*)(brow + 16);
            uint32_t bl0 = *(const uint32_t*)(brow + 2304);
            uint32_t bl1 = *(const uint32_t*)(brow + 2304 + 16);
            MMA_BF16(acc[nt], ah0, ah1, ah2, ah3, bh0, bh1);
            MMA_BF16(acc[nt], ah0, ah1, ah2, ah3, bl0, bl1);
            MMA_BF16(acc[nt], al0, al1, al2, al3, bh0, bh1);
        }
    }
    __syncthreads();   // A/B buffers dead -> HSO region may be written

    // D -> HSO[n][132][m]
    #pragma unroll
    for (int nt = 0; nt < 8; nt++) {
        int n0 = nt * 8 + 2 * t;
        int m0 = w * 16 + g;
        smf[n0 * 132 + m0]           = acc[nt][0];
        smf[(n0 + 1) * 132 + m0]     = acc[nt][1];
        smf[n0 * 132 + m0 + 8]       = acc[nt][2];
        smf[(n0 + 1) * 132 + m0 + 8] = acc[nt][3];
    }
    __syncthreads();

    // ---- stage 2 (per voxel, two 32x32 GEMMs) ----
    const int v = tid & 127, half = tid >> 7;
    const int obase = half * 16;

    float hv[32];
    #pragma unroll
    for (int jj = 0; jj < 32; jj++) {
        float tv = smf[jj * 132 + v] + smf[SWB_F + jj];
        hv[jj] = tv > 0.f ? tv : 0.2f * tv;
    }

    unsigned long long m2[8];
    {
        const unsigned long long* bmp =
            reinterpret_cast<const unsigned long long*>(smf + SWB_F + 64 + obase);
        #pragma unroll
        for (int p = 0; p < 8; p++) m2[p] = bmp[p];
    }
    #pragma unroll
    for (int jj = 0; jj < 32; jj++) {
        unsigned long long xj; BCAST(xj, hv[jj]);
        const unsigned long long* wr =
            reinterpret_cast<const unsigned long long*>(smf + SWB_F + 128 + jj * 32 + obase);
        #pragma unroll
        for (int p = 0; p < 8; p++) FMA2(m2[p], wr[p], xj);
    }
    #pragma unroll
    for (int p = 0; p < 8; p++) {
        float lo, hi; UNPK(lo, hi, m2[p]);
        lo = lo > 0.f ? lo : 0.2f * lo;
        hi = hi > 0.f ? hi : 0.2f * hi;
        smf[H2S_F + (obase + 2 * p) * 129 + v]     = lo;
        smf[H2S_F + (obase + 2 * p + 1) * 129 + v] = hi;
    }
    __syncthreads();

    unsigned long long f[8];
    {
        const unsigned long long* bop =
            reinterpret_cast<const unsigned long long*>(smf + SWB_F + 96 + obase);
        #pragma unroll
        for (int p = 0; p < 8; p++) f[p] = bop[p];
    }
    #pragma unroll
    for (int i = 0; i < 32; i++) {
        float h2 = smf[H2S_F + i * 129 + v];
        unsigned long long xi; BCAST(xi, h2);
        const unsigned long long* wr =
            reinterpret_cast<const unsigned long long*>(smf + SWB_F + 1152 + i * 32 + obase);
        #pragma unroll
        for (int p = 0; p < 8; p++) FMA2(f[p], wr[p], xi);
    }

    float* st = g_state + ((size_t)(b * NC) << 15) + v0 + v;
    #pragma unroll
    for (int p = 0; p < 8; p++) {
        float t0, t1; UNPK(t0, t1, f[p]);
        int o = obase + 2 * p;
        float s0 = smf[(32 + o) * 132 + v] + smf[SWB_F + 32 + o];
        float s1 = smf[(33 + o) * 132 + v] + smf[SWB_F + 33 + o];
        st[(size_t)o << 15]       += 0.1f * (t0 + s0);
        st[(size_t)(o + 1) << 15] += 0.1f * (t1 + s1);
    }
}

// ---------------- channel mean ----------------

__global__ void k_final(float* __restrict__ out) {
    int b = blockIdx.y;
    int v = (blockIdx.x << 8) + threadIdx.x;
    const float* st = g_state + b * NC * VOL + v;
    float s = 0.f;
    #pragma unroll
    for (int c = 0; c < NC; c++) s += st[c << 15];
    out[b * VOL + v] = s * (1.f / 32.f);
}

// ---------------- launch ----------------

extern "C" void kernel_launch(void* const* d_in, const int* in_sizes, int n_in,
                              void* d_out, int out_size) {
    const float* z  = (const float*)d_in[0];
    const int*   y  = (const int*)d_in[1];
    const float* hw = (const float*)d_in[2];
    const float* hb = (const float*)d_in[3];
    float* out = (float*)d_out;
    (void)in_sizes; (void)n_in; (void)out_size;

    cudaFuncSetAttribute(k_residual, cudaFuncAttributeMaxDynamicSharedMemorySize, RES_SMEM);

    k_norm<<<4, 256>>>(z);
    k_init<<<dim3(128, 4), 256>>>(z);
    k_theta<<<(BATCH * KT + 255) / 256, 256>>>(y, hw, hb);

    for (int it = 0; it < 4; it++) {
        k_sobel<<<dim3(32, 4), 512>>>();
        k_fold<<<4, 256>>>();
        k_residual<<<dim3(256, 4), 256, RES_SMEM>>>();
    }
    k_final<<<dim3(128, 4), 256>>>(out);
}

// round 8
// speedup vs baseline: 1.0416x; 1.0416x over previous
#include <cuda_runtime.h>
#include <cuda_bf16.h>
#include <cstdint>

#define BATCH 4
#define NC 32
#define CIN 224
#define VOL 32768
#define KT 16512

__device__ float  g_state[BATCH * NC * VOL];
__device__ float  g_feat [BATCH * CIN * VOL];
__device__ double g_sumd [BATCH * CIN];
__device__ double g_sqd  [BATCH * CIN];
__device__ float  g_zn   [BATCH];
__device__ float  g_theta[BATCH * KT];
__device__ float  g_w    [BATCH * KT];
__device__ __align__(16) float g_wdup[BATCH * 28672];  // stage1 weights, (w,w) pairs

// offsets (floats) inside per-batch g_w block
#define WC_OFF  0       // [224][64]: 0..31 = W_in', 32..63 = W_sh'
#define B64_OFF 14336
#define WM_OFF  14400
#define BM_OFF  15424
#define WO_OFF  15456
#define BO_OFF  16480

#define FMA2(acc, w, x) asm("fma.rn.f32x2 %0, %1, %2, %0;" : "+l"(acc) : "l"(w), "l"(x))
#define BCAST(d, f)     asm("mov.b64 %0, {%1, %1};" : "=l"(d) : "f"(f))
#define UNPK(lo, hi, q) asm("mov.b64 {%0, %1}, %2;" : "=f"(lo), "=f"(hi) : "l"(q))
#define CPA16(dst, src) asm volatile("cp.async.cg.shared.global [%0], [%1], 16;" :: "r"(dst), "l"(src))
#define CPCOMMIT()      asm volatile("cp.async.commit_group;")
#define CPWAIT(n)       asm volatile("cp.async.wait_group %0;" :: "n"(n))

// ---------------- setup ----------------

__global__ void k_norm(const float* __restrict__ z) {
    int b = blockIdx.x, t = threadIdx.x;
    float v0 = z[b * 512 + t], v1 = z[b * 512 + 256 + t];
    float s = v0 * v0 + v1 * v1;
    #pragma unroll
    for (int o = 16; o; o >>= 1) s += __shfl_down_sync(~0u, s, o);
    __shared__ float sh[8];
    if ((t & 31) == 0) sh[t >> 5] = s;
    __syncthreads();
    if (t < 8) {
        float x = sh[t];
        #pragma unroll
        for (int o = 4; o; o >>= 1) x += __shfl_down_sync(0xffu, x, o);
        if (t == 0) g_zn[b] = fmaxf(sqrtf(x), 1e-12f);
    }
}

__global__ void k_init(const float* __restrict__ z) {
    int b = blockIdx.y;
    int v = (blockIdx.x << 8) + threadIdx.x;
    float val = 0.f;
    if (v < 512) val = z[b * 512 + v] / g_zn[b];
    #pragma unroll
    for (int c = 0; c < NC; c++) g_state[((b * NC + c) << 15) + v] = val;
}

__global__ void k_theta(const int* __restrict__ y, const float* __restrict__ hw,
                        const float* __restrict__ hb) {
    int i = blockIdx.x * 256 + threadIdx.x;
    if (i >= BATCH * KT) return;
    int b = i / KT, k = i - b * KT;
    g_theta[i] = hw[y[b] * KT + k] + hb[k];
}

// ---------------- sobel (best-known from R5) ----------------

__global__ void __launch_bounds__(512) k_sobel() {
    __shared__ float sl[2][4][36][32];
    __shared__ float red[16][14];
    const int c = blockIdx.x, b = blockIdx.y;
    const int tid = threadIdx.x;
    const int lane = tid & 31, wid = tid >> 5;
    const int h0 = wid * 2;
    const float* __restrict__ xin = g_state + ((size_t)(b * NC + c) << 15);
    float* __restrict__ featb = g_feat + (size_t)(b * CIN + c) * VOL;

    for (int i = tid; i < 1024; i += 512) {
        int w = i & 31, r = (i >> 5) & 3, arr = (i >> 7) & 3, bu = i >> 9;
        int hp = (r < 2) ? r : r + 32;
        sl[bu][arr][hp][w] = 0.f;
    }

    const float R2 = 0.70710678118654752f;
    const float S1 = 1.f + R2;

    float stat[14];
    #pragma unroll
    for (int i = 0; i < 14; i++) stat[i] = 0.f;
    float W[2][6][5];
    #pragma unroll
    for (int r = 0; r < 2; r++)
        #pragma unroll
        for (int a = 0; a < 6; a++)
            #pragma unroll
            for (int k = 0; k < 5; k++) W[r][a][k] = 0.f;

    float xc[2];
    xc[0] = xin[((h0 + 0) << 5) + lane];
    xc[1] = xin[((h0 + 1) << 5) + lane];

    __syncthreads();

    float sw3[2], dw3[2], sw5[2], dw5[2];

    #pragma unroll 2
    for (int s = 0; s < 34; s++) {
        const int bu = s & 1;
        float xn0 = 0.f, xn1 = 0.f;
        if (s + 1 < 32) {
            xn0 = xin[((s + 1) << 10) + ((h0 + 0) << 5) + lane];
            xn1 = xin[((s + 1) << 10) + ((h0 + 1) << 5) + lane];
        }
        if (s < 32) {
            #pragma unroll
            for (int r = 0; r < 2; r++) {
                float xv = xc[r];
                stat[0] += xv; stat[1] += xv * xv;
                float xm1 = __shfl_up_sync(~0u, xv, 1);   if (lane == 0)  xm1 = 0.f;
                float xm2 = __shfl_up_sync(~0u, xv, 2);   if (lane < 2)   xm2 = 0.f;
                float xp1 = __shfl_down_sync(~0u, xv, 1); if (lane == 31) xp1 = 0.f;
                float xp2 = __shfl_down_sync(~0u, xv, 2); if (lane > 29)  xp2 = 0.f;
                sw3[r] = xm1 + 2.f * xv + xp1;
                dw3[r] = xp1 - xm1;
                sw5[r] = xm2 + xp2 + S1 * (xm1 + xp1) + 2.f * xv;
                dw5[r] = (xp2 - xm2) + R2 * (xp1 - xm1);
                int hp = h0 + r + 2;
                sl[bu][0][hp][lane] = sw3[r];
                sl[bu][1][hp][lane] = dw3[r];
                sl[bu][2][hp][lane] = sw5[r];
                sl[bu][3][hp][lane] = dw5[r];
            }
        }
        xc[0] = xn0; xc[1] = xn1;
        __syncthreads();
        #pragma unroll
        for (int r = 0; r < 2; r++) {
            float a30, a31, a32, a50, a51, a52;
            if (s < 32) {
                int hp = h0 + r + 2;
                float s3m = sl[bu][0][hp - 1][lane], s3p = sl[bu][0][hp + 1][lane];
                float d3m = sl[bu][1][hp - 1][lane], d3p = sl[bu][1][hp + 1][lane];
                float s5m2 = sl[bu][2][hp - 2][lane], s5m1 = sl[bu][2][hp - 1][lane];
                float s5p1 = sl[bu][2][hp + 1][lane], s5p2 = sl[bu][2][hp + 2][lane];
                float d5m2 = sl[bu][3][hp - 2][lane], d5m1 = sl[bu][3][hp - 1][lane];
                float d5p1 = sl[bu][3][hp + 1][lane], d5p2 = sl[bu][3][hp + 2][lane];
                a30 = d3m + 2.f * dw3[r] + d3p;
                a31 = s3p - s3m;
                a32 = s3m + 2.f * sw3[r] + s3p;
                a50 = d5m2 + d5p2 + S1 * (d5m1 + d5p1) + 2.f * dw5[r];
                a51 = (s5p2 - s5m2) + R2 * (s5p1 - s5m1);
                a52 = s5m2 + s5p2 + S1 * (s5m1 + s5p1) + 2.f * sw5[r];
            } else {
                a30 = a31 = a32 = a50 = a51 = a52 = 0.f;
            }
            #pragma unroll
            for (int a = 0; a < 6; a++) {
                W[r][a][0] = W[r][a][1]; W[r][a][1] = W[r][a][2];
                W[r][a][2] = W[r][a][3]; W[r][a][3] = W[r][a][4];
            }
            W[r][0][4] = a32; W[r][1][4] = a31; W[r][2][4] = a30;
            W[r][3][4] = a52; W[r][4][4] = a51; W[r][5][4] = a50;

            if (s >= 2) {
                int dc = s - 2;
                float o1 = W[r][0][3] - W[r][0][1];
                float o2 = W[r][1][1] + 2.f * W[r][1][2] + W[r][1][3];
                float o3 = W[r][2][1] + 2.f * W[r][2][2] + W[r][2][3];
                float o4 = (W[r][3][4] - W[r][3][0]) + R2 * (W[r][3][3] - W[r][3][1]);
                float o5 = W[r][4][0] + W[r][4][4] + S1 * (W[r][4][1] + W[r][4][3]) + 2.f * W[r][4][2];
                float o6 = W[r][5][0] + W[r][5][4] + S1 * (W[r][5][1] + W[r][5][3]) + 2.f * W[r][5][2];
                int v = (dc << 10) + ((h0 + r) << 5) + lane;
                featb[(size_t)32 * VOL + v]  = o1;
                featb[(size_t)64 * VOL + v]  = o2;
                featb[(size_t)96 * VOL + v]  = o3;
                featb[(size_t)128 * VOL + v] = o4;
                featb[(size_t)160 * VOL + v] = o5;
                featb[(size_t)192 * VOL + v] = o6;
                stat[2]  += o1; stat[3]  += o1 * o1;
                stat[4]  += o2; stat[5]  += o2 * o2;
                stat[6]  += o3; stat[7]  += o3 * o3;
                stat[8]  += o4; stat[9]  += o4 * o4;
                stat[10] += o5; stat[11] += o5 * o5;
                stat[12] += o6; stat[13] += o6 * o6;
            }
        }
    }

    #pragma unroll
    for (int i = 0; i < 14; i++) {
        float v = stat[i];
        #pragma unroll
        for (int o = 16; o; o >>= 1) v += __shfl_down_sync(~0u, v, o);
        stat[i] = v;
    }
    if (lane == 0)
        #pragma unroll
        for (int i = 0; i < 14; i++) red[wid][i] = stat[i];
    __syncthreads();
    if (tid < 14) {
        double acc = 0.0;
        #pragma unroll
        for (int k = 0; k < 16; k++) acc += (double)red[k][tid];
        int g = tid >> 1;
        if (tid & 1) g_sqd [b * CIN + g * 32 + c] = acc;
        else         g_sumd[b * CIN + g * 32 + c] = acc;
    }
}

// ------- fold norm into weights + build duplicated stage1 weight image -------
// g_wdup per batch: [chunk 14][kk 16][o 64 as (w,w) pairs] = 28672 floats

__global__ void k_fold() {
    int b = blockIdx.x, tid = threadIdx.x;
    int lane = tid & 31, wid = tid >> 5;
    __shared__ float smean[CIN], srs[CIN];
    if (tid < CIN) {
        double m = g_sumd[b * CIN + tid] * (1.0 / 32768.0);
        double var = g_sqd[b * CIN + tid] * (1.0 / 32768.0) - m * m;
        smean[tid] = (float)m;
        srs[tid] = (float)rsqrt(var + 1e-5);
    }
    __syncthreads();
    const float* th = g_theta + b * KT;
    float* w = g_w + b * KT;
    #pragma unroll
    for (int j = 0; j < 8; j++) {
        int o = wid * 8 + j;
        int off = (o < 32) ? o * 224 : 9312 + (o - 32) * 224;
        float corr = 0.f;
        #pragma unroll
        for (int q = 0; q < 7; q++) {
            int cc = lane + q * 32;
            float wv = th[off + cc] * srs[cc];
            w[WC_OFF + cc * 64 + o] = wv;
            corr += wv * smean[cc];
        }
        #pragma unroll
        for (int d = 16; d; d >>= 1) corr += __shfl_down_sync(~0u, corr, d);
        if (lane == 0) {
            float braw = (o < 32) ? th[7168 + o] : th[16480 + o - 32];
            w[B64_OFF + o] = braw - corr;
        }
    }
    for (int i = tid; i < 1024; i += 256) {
        int r = i >> 5, cc = i & 31;
        w[WM_OFF + cc * 32 + r] = th[7200 + r * 32 + cc];
        w[WO_OFF + cc * 32 + r] = th[8256 + r * 32 + cc];
    }
    if (tid < 32) {
        w[BM_OFF + tid] = th[8224 + tid];
        w[BO_OFF + tid] = th[9280 + tid];
    }
    __syncthreads();
    float* wd = g_wdup + b * 28672;
    for (int i = tid; i < 14336; i += 256) {
        // i = cc*64 + o, cc in [0,224), o in [0,64)
        int cc = i >> 6, o = i & 63;
        float val = w[WC_OFF + cc * 64 + o];
        wd[cc * 128 + o * 2]     = val;
        wd[cc * 128 + o * 2 + 1] = val;
    }
}

// ---------------- register-blocked residual MLP (voxel-paired accs) ----------
// block: 64 outputs x 128 voxels, 256 threads; thread = 8 out x 4 vox
// acc[o][p] packs voxels (lane*4+2p, lane*4+2p+1) -> x pair straight from LDS.128
// w pre-duplicated -> warp-uniform LDS.128 covers 2 outputs, no BCAST movs.
// smem floats: ring [3][x 2048 | w 2048] at 0; SWB at 12288; H2S at 14464
// HSO [64][132] unions ring after stage 1.
#define SWB_F 12288
#define H2S_F 14464
#define SM_FLOATS 18592

__global__ void __launch_bounds__(256) k_residual() {
    extern __shared__ __align__(16) float smf[];
    const int tid = threadIdx.x;
    const int wid = tid >> 5, lane = tid & 31;
    const int b = blockIdx.y;
    const int v0 = blockIdx.x << 7;
    const float* gw = g_w + b * KT;
    uint32_t swa;
    asm("{ .reg .u64 tt; cvta.to.shared.u64 tt, %1; cvt.u32.u64 %0, tt; }"
        : "=r"(swa) : "l"(smf));

    // stage-2 weights -> smem
    if (tid < 64)  smf[SWB_F + tid]      = gw[B64_OFF + tid];
    if (tid < 32)  smf[SWB_F + 64 + tid] = gw[BM_OFF + tid];
    if (tid >= 32 && tid < 64) smf[SWB_F + 96 + (tid - 32)] = gw[BO_OFF + tid - 32];
    for (int i = tid; i < 1024; i += 256) smf[SWB_F + 128 + i]  = gw[WM_OFF + i];
    for (int i = tid; i < 1024; i += 256) smf[SWB_F + 1152 + i] = gw[WO_OFF + i];

    const int xrow0 = tid >> 5, clw = tid & 31;
    auto issue = [&](int ch) {
        int slot = ch % 3;
        int cc0 = ch * 16 + xrow0;
        const float* xsrc0 = (cc0 < 32)
            ? g_state + ((size_t)(b * NC + cc0) << 15) + v0 + clw * 4
            : g_feat  + ((size_t)(b * CIN + cc0) << 15) + v0 + clw * 4;
        CPA16(swa + (slot * 4096 + xrow0 * 128 + clw * 4) * 4, xsrc0);
        int cc1 = cc0 + 8;
        const float* xsrc1 = (cc1 < 32)
            ? g_state + ((size_t)(b * NC + cc1) << 15) + v0 + clw * 4
            : g_feat  + ((size_t)(b * CIN + cc1) << 15) + v0 + clw * 4;
        CPA16(swa + (slot * 4096 + (xrow0 + 8) * 128 + clw * 4) * 4, xsrc1);
        const float* wsrc = g_wdup + b * 28672 + ch * 2048 + tid * 8;
        uint32_t wdst = swa + (slot * 4096 + 2048 + tid * 8) * 4;
        CPA16(wdst, wsrc);
        CPA16(wdst + 16, wsrc + 4);
    };

    issue(0); CPCOMMIT();
    issue(1); CPCOMMIT();

    unsigned long long acc[16];
    #pragma unroll
    for (int i = 0; i < 16; i++) acc[i] = 0ull;

    for (int ch = 0; ch < 14; ch++) {
        if (ch < 13) CPWAIT(1); else CPWAIT(0);
        __syncthreads();
        if (ch + 2 < 14) { issue(ch + 2); CPCOMMIT(); }
        const float* xb = smf + (ch % 3) * 4096;
        const float* wb = xb + 2048;
        #pragma unroll
        for (int kk = 0; kk < 16; kk++) {
            ulonglong2 xp = *reinterpret_cast<const ulonglong2*>(xb + kk * 128 + lane * 4);
            const ulonglong2* wp =
                reinterpret_cast<const ulonglong2*>(wb + kk * 128 + wid * 16);
            ulonglong2 w01 = wp[0], w23 = wp[1], w45 = wp[2], w67 = wp[3];
            FMA2(acc[0],  w01.x, xp.x); FMA2(acc[1],  w01.x, xp.y);
            FMA2(acc[2],  w01.y, xp.x); FMA2(acc[3],  w01.y, xp.y);
            FMA2(acc[4],  w23.x, xp.x); FMA2(acc[5],  w23.x, xp.y);
            FMA2(acc[6],  w23.y, xp.x); FMA2(acc[7],  w23.y, xp.y);
            FMA2(acc[8],  w45.x, xp.x); FMA2(acc[9],  w45.x, xp.y);
            FMA2(acc[10], w45.y, xp.x); FMA2(acc[11], w45.y, xp.y);
            FMA2(acc[12], w67.x, xp.x); FMA2(acc[13], w67.x, xp.y);
            FMA2(acc[14], w67.y, xp.x); FMA2(acc[15], w67.y, xp.y);
        }
    }
    __syncthreads();   // ring dead -> HSO region may be written

    // acc[o*2+p] = outputs wid*8+o, voxels (lane*4+2p, +1) -> HSO[o][132]
    #pragma unroll
    for (int o = 0; o < 8; o++) {
        float l0, h0v, l1, h1v;
        UNPK(l0, h0v, acc[o * 2]);
        UNPK(l1, h1v, acc[o * 2 + 1]);
        float* row = smf + (wid * 8 + o) * 132 + lane * 4;
        *reinterpret_cast<float2*>(row)     = make_float2(l0, h0v);
        *reinterpret_cast<float2*>(row + 2) = make_float2(l1, h1v);
    }
    __syncthreads();

    // ---- stage 2 (per voxel, two 32x32 GEMMs; biases added here) ----
    const int v = tid & 127, half = tid >> 7;
    const int obase = half * 16;

    float hv[32];
    #pragma unroll
    for (int jj = 0; jj < 32; jj++) {
        float tv = smf[jj * 132 + v] + smf[SWB_F + jj];
        hv[jj] = tv > 0.f ? tv : 0.2f * tv;
    }

    unsigned long long m2[8];
    {
        const unsigned long long* bmp =
            reinterpret_cast<const unsigned long long*>(smf + SWB_F + 64 + obase);
        #pragma unroll
        for (int p = 0; p < 8; p++) m2[p] = bmp[p];
    }
    #pragma unroll
    for (int jj = 0; jj < 32; jj++) {
        unsigned long long xj; BCAST(xj, hv[jj]);
        const unsigned long long* wr =
            reinterpret_cast<const unsigned long long*>(smf + SWB_F + 128 + jj * 32 + obase);
        #pragma unroll
        for (int p = 0; p < 8; p++) FMA2(m2[p], wr[p], xj);
    }
    #pragma unroll
    for (int p = 0; p < 8; p++) {
        float lo, hi; UNPK(lo, hi, m2[p]);
        lo = lo > 0.f ? lo : 0.2f * lo;
        hi = hi > 0.f ? hi : 0.2f * hi;
        smf[H2S_F + (obase + 2 * p) * 129 + v]     = lo;
        smf[H2S_F + (obase + 2 * p + 1) * 129 + v] = hi;
    }
    __syncthreads();

    unsigned long long f[8];
    {
        const unsigned long long* bop =
            reinterpret_cast<const unsigned long long*>(smf + SWB_F + 96 + obase);
        #pragma unroll
        for (int p = 0; p < 8; p++) f[p] = bop[p];
    }
    #pragma unroll
    for (int i = 0; i < 32; i++) {
        float h2 = smf[H2S_F + i * 129 + v];
        unsigned long long xi; BCAST(xi, h2);
        const unsigned long long* wr =
            reinterpret_cast<const unsigned long long*>(smf + SWB_F + 1152 + i * 32 + obase);
        #pragma unroll
        for (int p = 0; p < 8; p++) FMA2(f[p], wr[p], xi);
    }

    float* st = g_state + ((size_t)(b * NC) << 15) + v0 + v;
    #pragma unroll
    for (int p = 0; p < 8; p++) {
        float t0, t1; UNPK(t0, t1, f[p]);
        int o = obase + 2 * p;
        float s0 = smf[(32 + o) * 132 + v] + smf[SWB_F + 32 + o];
        float s1 = smf[(33 + o) * 132 + v] + smf[SWB_F + 33 + o];
        st[(size_t)o << 15]       += 0.1f * (t0 + s0);
        st[(size_t)(o + 1) << 15] += 0.1f * (t1 + s1);
    }
}

// ---------------- channel mean ----------------

__global__ void k_final(float* __restrict__ out) {
    int b = blockIdx.y;
    int v = (blockIdx.x << 8) + threadIdx.x;
    const float* st = g_state + b * NC * VOL + v;
    float s = 0.f;
    #pragma unroll
    for (int c = 0; c < NC; c++) s += st[c << 15];
    out[b * VOL + v] = s * (1.f / 32.f);
}

// ---------------- launch ----------------

extern "C" void kernel_launch(void* const* d_in, const int* in_sizes, int n_in,
                              void* d_out, int out_size) {
    const float* z  = (const float*)d_in[0];
    const int*   y  = (const int*)d_in[1];
    const float* hw = (const float*)d_in[2];
    const float* hb = (const float*)d_in[3];
    float* out = (float*)d_out;
    (void)in_sizes; (void)n_in; (void)out_size;

    cudaFuncSetAttribute(k_residual, cudaFuncAttributeMaxDynamicSharedMemorySize,
                         SM_FLOATS * 4);

    k_norm<<<4, 256>>>(z);
    k_init<<<dim3(128, 4), 256>>>(z);
    k_theta<<<(BATCH * KT + 255) / 256, 256>>>(y, hw, hb);

    for (int it = 0; it < 4; it++) {
        k_sobel<<<dim3(32, 4), 512>>>();
        k_fold<<<4, 256>>>();
        k_residual<<<dim3(256, 4), 256, SM_FLOATS * 4>>>();
    }
    k_final<<<dim3(128, 4), 256>>>(out);
}

// round 9
// speedup vs baseline: 1.0728x; 1.0300x over previous
#include <cuda_runtime.h>
#include <cuda_bf16.h>
#include <cstdint>

#define BATCH 4
#define NC 32
#define CIN 224
#define VOL 32768
#define KT 16512

__device__ float  g_state[BATCH * NC * VOL];
__device__ float  g_feat [BATCH * CIN * VOL];
__device__ double g_sumd [BATCH * CIN];
__device__ double g_sqd  [BATCH * CIN];
__device__ float  g_zn   [BATCH];
__device__ float  g_theta[BATCH * KT];
__device__ float  g_w    [BATCH * KT];

// offsets (floats) inside per-batch g_w block (same layout mirrored in smem)
#define WC_OFF  0       // [224 k][64 o]: o 0..31 = W_in', 32..63 = W_sh'
#define B64_OFF 14336
#define WM_OFF  14400
#define BM_OFF  15424
#define WO_OFF  15456
#define BO_OFF  16480

#define FMA2(acc, w, x) asm("fma.rn.f32x2 %0, %1, %2, %0;" : "+l"(acc) : "l"(w), "l"(x))
#define BCAST(d, f)     asm("mov.b64 %0, {%1, %1};" : "=l"(d) : "f"(f))
#define UNPK(lo, hi, q) asm("mov.b64 {%0, %1}, %2;" : "=f"(lo), "=f"(hi) : "l"(q))

// ---------------- setup ----------------

__global__ void k_norm(const float* __restrict__ z) {
    int b = blockIdx.x, t = threadIdx.x;
    float v0 = z[b * 512 + t], v1 = z[b * 512 + 256 + t];
    float s = v0 * v0 + v1 * v1;
    #pragma unroll
    for (int o = 16; o; o >>= 1) s += __shfl_down_sync(~0u, s, o);
    __shared__ float sh[8];
    if ((t & 31) == 0) sh[t >> 5] = s;
    __syncthreads();
    if (t < 8) {
        float x = sh[t];
        #pragma unroll
        for (int o = 4; o; o >>= 1) x += __shfl_down_sync(0xffu, x, o);
        if (t == 0) g_zn[b] = fmaxf(sqrtf(x), 1e-12f);
    }
}

__global__ void k_init(const float* __restrict__ z) {
    int b = blockIdx.y;
    int v = (blockIdx.x << 8) + threadIdx.x;
    float val = 0.f;
    if (v < 512) val = z[b * 512 + v] / g_zn[b];
    #pragma unroll
    for (int c = 0; c < NC; c++) g_state[((b * NC + c) << 15) + v] = val;
}

__global__ void k_theta(const int* __restrict__ y, const float* __restrict__ hw,
                        const float* __restrict__ hb) {
    int i = blockIdx.x * 256 + threadIdx.x;
    if (i >= BATCH * KT) return;
    int b = i / KT, k = i - b * KT;
    g_theta[i] = hw[y[b] * KT + k] + hb[k];
}

// ---------------- sobel (writes identity channel too) ----------------

__global__ void __launch_bounds__(512) k_sobel() {
    __shared__ float sl[2][4][36][32];
    __shared__ float red[16][14];
    const int c = blockIdx.x, b = blockIdx.y;
    const int tid = threadIdx.x;
    const int lane = tid & 31, wid = tid >> 5;
    const int h0 = wid * 2;
    const float* __restrict__ xin = g_state + ((size_t)(b * NC + c) << 15);
    float* __restrict__ featb = g_feat + (size_t)(b * CIN + c) * VOL;

    for (int i = tid; i < 1024; i += 512) {
        int w = i & 31, r = (i >> 5) & 3, arr = (i >> 7) & 3, bu = i >> 9;
        int hp = (r < 2) ? r : r + 32;
        sl[bu][arr][hp][w] = 0.f;
    }

    const float R2 = 0.70710678118654752f;
    const float S1 = 1.f + R2;

    float stat[14];
    #pragma unroll
    for (int i = 0; i < 14; i++) stat[i] = 0.f;
    float W[2][6][5];
    #pragma unroll
    for (int r = 0; r < 2; r++)
        #pragma unroll
        for (int a = 0; a < 6; a++)
            #pragma unroll
            for (int k = 0; k < 5; k++) W[r][a][k] = 0.f;

    float xc[2];
    xc[0] = xin[((h0 + 0) << 5) + lane];
    xc[1] = xin[((h0 + 1) << 5) + lane];

    __syncthreads();

    float sw3[2], dw3[2], sw5[2], dw5[2];

    #pragma unroll 2
    for (int s = 0; s < 34; s++) {
        const int bu = s & 1;
        float xn0 = 0.f, xn1 = 0.f;
        if (s + 1 < 32) {
            xn0 = xin[((s + 1) << 10) + ((h0 + 0) << 5) + lane];
            xn1 = xin[((s + 1) << 10) + ((h0 + 1) << 5) + lane];
        }
        if (s < 32) {
            #pragma unroll
            for (int r = 0; r < 2; r++) {
                float xv = xc[r];
                stat[0] += xv; stat[1] += xv * xv;
                float xm1 = __shfl_up_sync(~0u, xv, 1);   if (lane == 0)  xm1 = 0.f;
                float xm2 = __shfl_up_sync(~0u, xv, 2);   if (lane < 2)   xm2 = 0.f;
                float xp1 = __shfl_down_sync(~0u, xv, 1); if (lane == 31) xp1 = 0.f;
                float xp2 = __shfl_down_sync(~0u, xv, 2); if (lane > 29)  xp2 = 0.f;
                sw3[r] = xm1 + 2.f * xv + xp1;
                dw3[r] = xp1 - xm1;
                sw5[r] = xm2 + xp2 + S1 * (xm1 + xp1) + 2.f * xv;
                dw5[r] = (xp2 - xm2) + R2 * (xp1 - xm1);
                int hp = h0 + r + 2;
                sl[bu][0][hp][lane] = sw3[r];
                sl[bu][1][hp][lane] = dw3[r];
                sl[bu][2][hp][lane] = sw5[r];
                sl[bu][3][hp][lane] = dw5[r];
                // identity channel store (d-slice s)
                featb[(s << 10) + ((h0 + r) << 5) + lane] = xv;
            }
        }
        xc[0] = xn0; xc[1] = xn1;
        __syncthreads();
        #pragma unroll
        for (int r = 0; r < 2; r++) {
            float a30, a31, a32, a50, a51, a52;
            if (s < 32) {
                int hp = h0 + r + 2;
                float s3m = sl[bu][0][hp - 1][lane], s3p = sl[bu][0][hp + 1][lane];
                float d3m = sl[bu][1][hp - 1][lane], d3p = sl[bu][1][hp + 1][lane];
                float s5m2 = sl[bu][2][hp - 2][lane], s5m1 = sl[bu][2][hp - 1][lane];
                float s5p1 = sl[bu][2][hp + 1][lane], s5p2 = sl[bu][2][hp + 2][lane];
                float d5m2 = sl[bu][3][hp - 2][lane], d5m1 = sl[bu][3][hp - 1][lane];
                float d5p1 = sl[bu][3][hp + 1][lane], d5p2 = sl[bu][3][hp + 2][lane];
                a30 = d3m + 2.f * dw3[r] + d3p;
                a31 = s3p - s3m;
                a32 = s3m + 2.f * sw3[r] + s3p;
                a50 = d5m2 + d5p2 + S1 * (d5m1 + d5p1) + 2.f * dw5[r];
                a51 = (s5p2 - s5m2) + R2 * (s5p1 - s5m1);
                a52 = s5m2 + s5p2 + S1 * (s5m1 + s5p1) + 2.f * sw5[r];
            } else {
                a30 = a31 = a32 = a50 = a51 = a52 = 0.f;
            }
            #pragma unroll
            for (int a = 0; a < 6; a++) {
                W[r][a][0] = W[r][a][1]; W[r][a][1] = W[r][a][2];
                W[r][a][2] = W[r][a][3]; W[r][a][3] = W[r][a][4];
            }
            W[r][0][4] = a32; W[r][1][4] = a31; W[r][2][4] = a30;
            W[r][3][4] = a52; W[r][4][4] = a51; W[r][5][4] = a50;

            if (s >= 2) {
                int dc = s - 2;
                float o1 = W[r][0][3] - W[r][0][1];
                float o2 = W[r][1][1] + 2.f * W[r][1][2] + W[r][1][3];
                float o3 = W[r][2][1] + 2.f * W[r][2][2] + W[r][2][3];
                float o4 = (W[r][3][4] - W[r][3][0]) + R2 * (W[r][3][3] - W[r][3][1]);
                float o5 = W[r][4][0] + W[r][4][4] + S1 * (W[r][4][1] + W[r][4][3]) + 2.f * W[r][4][2];
                float o6 = W[r][5][0] + W[r][5][4] + S1 * (W[r][5][1] + W[r][5][3]) + 2.f * W[r][5][2];
                int v = (dc << 10) + ((h0 + r) << 5) + lane;
                featb[(size_t)32 * VOL + v]  = o1;
                featb[(size_t)64 * VOL + v]  = o2;
                featb[(size_t)96 * VOL + v]  = o3;
                featb[(size_t)128 * VOL + v] = o4;
                featb[(size_t)160 * VOL + v] = o5;
                featb[(size_t)192 * VOL + v] = o6;
                stat[2]  += o1; stat[3]  += o1 * o1;
                stat[4]  += o2; stat[5]  += o2 * o2;
                stat[6]  += o3; stat[7]  += o3 * o3;
                stat[8]  += o4; stat[9]  += o4 * o4;
                stat[10] += o5; stat[11] += o5 * o5;
                stat[12] += o6; stat[13] += o6 * o6;
            }
        }
    }

    #pragma unroll
    for (int i = 0; i < 14; i++) {
        float v = stat[i];
        #pragma unroll
        for (int o = 16; o; o >>= 1) v += __shfl_down_sync(~0u, v, o);
        stat[i] = v;
    }
    if (lane == 0)
        #pragma unroll
        for (int i = 0; i < 14; i++) red[wid][i] = stat[i];
    __syncthreads();
    if (tid < 14) {
        double acc = 0.0;
        #pragma unroll
        for (int k = 0; k < 16; k++) acc += (double)red[k][tid];
        int g = tid >> 1;
        if (tid & 1) g_sqd [b * CIN + g * 32 + c] = acc;
        else         g_sumd[b * CIN + g * 32 + c] = acc;
    }
}

// ---------------- fold norm into weights ----------------

__global__ void k_fold() {
    int b = blockIdx.x, tid = threadIdx.x;
    int lane = tid & 31, wid = tid >> 5;
    __shared__ float smean[CIN], srs[CIN];
    if (tid < CIN) {
        double m = g_sumd[b * CIN + tid] * (1.0 / 32768.0);
        double var = g_sqd[b * CIN + tid] * (1.0 / 32768.0) - m * m;
        smean[tid] = (float)m;
        srs[tid] = (float)rsqrt(var + 1e-5);
    }
    __syncthreads();
    const float* th = g_theta + b * KT;
    float* w = g_w + b * KT;
    #pragma unroll
    for (int j = 0; j < 8; j++) {
        int o = wid * 8 + j;
        int off = (o < 32) ? o * 224 : 9312 + (o - 32) * 224;
        float corr = 0.f;
        #pragma unroll
        for (int q = 0; q < 7; q++) {
            int cc = lane + q * 32;
            float wv = th[off + cc] * srs[cc];
            w[WC_OFF + cc * 64 + o] = wv;
            corr += wv * smean[cc];
        }
        #pragma unroll
        for (int d = 16; d; d >>= 1) corr += __shfl_down_sync(~0u, corr, d);
        if (lane == 0) {
            float braw = (o < 32) ? th[7168 + o] : th[16480 + o - 32];
            w[B64_OFF + o] = braw - corr;
        }
    }
    for (int i = tid; i < 1024; i += 256) {
        int r = i >> 5, cc = i & 31;
        w[WM_OFF + cc * 32 + r] = th[7200 + r * 32 + cc];
        w[WO_OFF + cc * 32 + r] = th[8256 + r * 32 + cc];
    }
    if (tid < 32) {
        w[BM_OFF + tid] = th[8224 + tid];
        w[BO_OFF + tid] = th[9280 + tid];
    }
}

// ---------------- residual MLP: barrier-free stage-1 k-loop ----------------
// block: 64 outputs x 128 voxels, 256 threads; thread = 8 out x 4 vox
// All 16512 weight floats mirrored to smem once. x streamed via pipelined LDG.
// HSO [64][132] + H2S [32][129] union into dead WC region after stage 1.
#define HSO_F 0
#define H2S_F 8448
#define SM_FLOATS 16512

__global__ void __launch_bounds__(256) k_residual() {
    extern __shared__ __align__(16) float smf[];
    const int tid = threadIdx.x;
    const int wid = tid >> 5, lane = tid & 31;
    const int b = blockIdx.y;
    const int v0 = blockIdx.x << 7;
    const float* gw = g_w + b * KT;

    // x prologue: start depth-8 LDG pipeline before the weight barrier
    const float* xp = g_feat + ((size_t)(b * CIN) << 15) + v0 + lane * 4;
    float4 xb[8];
    #pragma unroll
    for (int i = 0; i < 8; i++)
        xb[i] = *reinterpret_cast<const float4*>(xp + ((size_t)i << 15));

    // full weight block -> smem (same offsets as g_w)
    {
        const float4* src = reinterpret_cast<const float4*>(gw);
        float4* dst = reinterpret_cast<float4*>(smf);
        for (int i = tid; i < KT / 4; i += 256) dst[i] = src[i];
    }
    __syncthreads();

    unsigned long long acc[16];
    #pragma unroll
    for (int i = 0; i < 16; i++) acc[i] = 0ull;

    const float* wrow = smf + wid * 8;   // + k*64 per step (warp-uniform)

    // main loop: k = 0..215 with prefetch k+8; tail 216..223 without
    #pragma unroll 8
    for (int k = 0; k < 216; k++) {
        float4 xv = xb[k & 7];
        xb[k & 7] = *reinterpret_cast<const float4*>(xp + ((size_t)(k + 8) << 15));
        unsigned long long xq0, xq1, xq2, xq3;
        BCAST(xq0, xv.x); BCAST(xq1, xv.y); BCAST(xq2, xv.z); BCAST(xq3, xv.w);
        const ulonglong2* wp = reinterpret_cast<const ulonglong2*>(wrow + k * 64);
        ulonglong2 wA = wp[0], wB = wp[1];
        FMA2(acc[0],  wA.x, xq0); FMA2(acc[1],  wA.x, xq1);
        FMA2(acc[2],  wA.x, xq2); FMA2(acc[3],  wA.x, xq3);
        FMA2(acc[4],  wA.y, xq0); FMA2(acc[5],  wA.y, xq1);
        FMA2(acc[6],  wA.y, xq2); FMA2(acc[7],  wA.y, xq3);
        FMA2(acc[8],  wB.x, xq0); FMA2(acc[9],  wB.x, xq1);
        FMA2(acc[10], wB.x, xq2); FMA2(acc[11], wB.x, xq3);
        FMA2(acc[12], wB.y, xq0); FMA2(acc[13], wB.y, xq1);
        FMA2(acc[14], wB.y, xq2); FMA2(acc[15], wB.y, xq3);
    }
    #pragma unroll
    for (int k = 216; k < 224; k++) {
        float4 xv = xb[k & 7];
        unsigned long long xq0, xq1, xq2, xq3;
        BCAST(xq0, xv.x); BCAST(xq1, xv.y); BCAST(xq2, xv.z); BCAST(xq3, xv.w);
        const ulonglong2* wp = reinterpret_cast<const ulonglong2*>(wrow + k * 64);
        ulonglong2 wA = wp[0], wB = wp[1];
        FMA2(acc[0],  wA.x, xq0); FMA2(acc[1],  wA.x, xq1);
        FMA2(acc[2],  wA.x, xq2); FMA2(acc[3],  wA.x, xq3);
        FMA2(acc[4],  wA.y, xq0); FMA2(acc[5],  wA.y, xq1);
        FMA2(acc[6],  wA.y, xq2); FMA2(acc[7],  wA.y, xq3);
        FMA2(acc[8],  wB.x, xq0); FMA2(acc[9],  wB.x, xq1);
        FMA2(acc[10], wB.x, xq2); FMA2(acc[11], wB.x, xq3);
        FMA2(acc[12], wB.y, xq0); FMA2(acc[13], wB.y, xq1);
        FMA2(acc[14], wB.y, xq2); FMA2(acc[15], wB.y, xq3);
    }
    __syncthreads();   // WC reads done -> HSO region may be written

    // acc[j*4+q] = outputs (wid*8+2j, +1), voxel lane*4+q -> HSO rows
    #pragma unroll
    for (int j = 0; j < 4; j++) {
        float lo0, hi0, lo1, hi1, lo2, hi2, lo3, hi3;
        UNPK(lo0, hi0, acc[j * 4 + 0]); UNPK(lo1, hi1, acc[j * 4 + 1]);
        UNPK(lo2, hi2, acc[j * 4 + 2]); UNPK(lo3, hi3, acc[j * 4 + 3]);
        int o = wid * 8 + 2 * j;
        *reinterpret_cast<float4*>(smf + HSO_F + o * 132 + lane * 4)
            = make_float4(lo0, lo1, lo2, lo3);
        *reinterpret_cast<float4*>(smf + HSO_F + (o + 1) * 132 + lane * 4)
            = make_float4(hi0, hi1, hi2, hi3);
    }
    __syncthreads();

    // ---- stage 2 (per voxel, two 32x32 GEMMs; stage-1 biases added here) ----
    const int v = tid & 127, half = tid >> 7;
    const int obase = half * 16;

    float hv[32];
    #pragma unroll
    for (int jj = 0; jj < 32; jj++) {
        float tv = smf[HSO_F + jj * 132 + v] + smf[B64_OFF + jj];
        hv[jj] = tv > 0.f ? tv : 0.2f * tv;
    }

    unsigned long long m2[8];
    {
        const unsigned long long* bmp =
            reinterpret_cast<const unsigned long long*>(smf + BM_OFF + obase);
        #pragma unroll
        for (int p = 0; p < 8; p++) m2[p] = bmp[p];
    }
    #pragma unroll
    for (int jj = 0; jj < 32; jj++) {
        unsigned long long xj; BCAST(xj, hv[jj]);
        const unsigned long long* wr =
            reinterpret_cast<const unsigned long long*>(smf + WM_OFF + jj * 32 + obase);
        #pragma unroll
        for (int p = 0; p < 8; p++) FMA2(m2[p], wr[p], xj);
    }
    #pragma unroll
    for (int p = 0; p < 8; p++) {
        float lo, hi; UNPK(lo, hi, m2[p]);
        lo = lo > 0.f ? lo : 0.2f * lo;
        hi = hi > 0.f ? hi : 0.2f * hi;
        smf[H2S_F + (obase + 2 * p) * 129 + v]     = lo;
        smf[H2S_F + (obase + 2 * p + 1) * 129 + v] = hi;
    }
    __syncthreads();

    unsigned long long f[8];
    {
        const unsigned long long* bop =
            reinterpret_cast<const unsigned long long*>(smf + BO_OFF + obase);
        #pragma unroll
        for (int p = 0; p < 8; p++) f[p] = bop[p];
    }
    #pragma unroll
    for (int i = 0; i < 32; i++) {
        float h2 = smf[H2S_F + i * 129 + v];
        unsigned long long xi; BCAST(xi, h2);
        const unsigned long long* wr =
            reinterpret_cast<const unsigned long long*>(smf + WO_OFF + i * 32 + obase);
        #pragma unroll
        for (int p = 0; p < 8; p++) FMA2(f[p], wr[p], xi);
    }

    float* st = g_state + ((size_t)(b * NC) << 15) + v0 + v;
    #pragma unroll
    for (int p = 0; p < 8; p++) {
        float t0, t1; UNPK(t0, t1, f[p]);
        int o = obase + 2 * p;
        float s0 = smf[HSO_F + (32 + o) * 132 + v] + smf[B64_OFF + 32 + o];
        float s1 = smf[HSO_F + (33 + o) * 132 + v] + smf[B64_OFF + 33 + o];
        st[(size_t)o << 15]       += 0.1f * (t0 + s0);
        st[(size_t)(o + 1) << 15] += 0.1f * (t1 + s1);
    }
}

// ---------------- channel mean ----------------

__global__ void k_final(float* __restrict__ out) {
    int b = blockIdx.y;
    int v = (blockIdx.x << 8) + threadIdx.x;
    const float* st = g_state + b * NC * VOL + v;
    float s = 0.f;
    #pragma unroll
    for (int c = 0; c < NC; c++) s += st[c << 15];
    out[b * VOL + v] = s * (1.f / 32.f);
}

// ---------------- launch ----------------

extern "C" void kernel_launch(void* const* d_in, const int* in_sizes, int n_in,
                              void* d_out, int out_size) {
    const float* z  = (const float*)d_in[0];
    const int*   y  = (const int*)d_in[1];
    const float* hw = (const float*)d_in[2];
    const float* hb = (const float*)d_in[3];
    float* out = (float*)d_out;
    (void)in_sizes; (void)n_in; (void)out_size;

    cudaFuncSetAttribute(k_residual, cudaFuncAttributeMaxDynamicSharedMemorySize,
                         SM_FLOATS * 4);

    k_norm<<<4, 256>>>(z);
    k_init<<<dim3(128, 4), 256>>>(z);
    k_theta<<<(BATCH * KT + 255) / 256, 256>>>(y, hw, hb);

    for (int it = 0; it < 4; it++) {
        k_sobel<<<dim3(32, 4), 512>>>();
        k_fold<<<4, 256>>>();
        k_residual<<<dim3(256, 4), 256, SM_FLOATS * 4>>>();
    }
    k_final<<<dim3(128, 4), 256>>>(out);
}

// round 10
// speedup vs baseline: 1.4482x; 1.3499x over previous
#include <cuda_runtime.h>
#include <cuda_bf16.h>
#include <cstdint>

#define BATCH 4
#define NC 32
#define CIN 224
#define VOL 32768
#define KT 16512

__device__ float  g_state[BATCH * NC * VOL];
__device__ float  g_feat [BATCH * CIN * VOL];
__device__ double g_sumd [BATCH * CIN];
__device__ double g_sqd  [BATCH * CIN];
__device__ float  g_w    [BATCH * KT];

// offsets (floats) inside per-batch g_w block
#define WC_OFF  0       // [224 k][64 o]: o 0..31 = W_in', 32..63 = W_sh'
#define B64_OFF 14336
#define WM_OFF  14400
#define BM_OFF  15424
#define WO_OFF  15456
#define BO_OFF  16480

#define FMA2(acc, w, x) asm("fma.rn.f32x2 %0, %1, %2, %0;" : "+l"(acc) : "l"(w), "l"(x))
#define BCAST(d, f)     asm("mov.b64 %0, {%1, %1};" : "=l"(d) : "f"(f))
#define UNPK(lo, hi, q) asm("mov.b64 {%0, %1}, %2;" : "=f"(lo), "=f"(hi) : "l"(q))
#define CPA16(dst, src) asm volatile("cp.async.cg.shared.global [%0], [%1], 16;" :: "r"(dst), "l"(src))
#define CPCOMMIT()      asm volatile("cp.async.commit_group;")
#define CPWAIT(n)       asm volatile("cp.async.wait_group %0;" :: "n"(n))

// ---------------- init (z-normalize inline) ----------------

__global__ void k_init(const float* __restrict__ z) {
    int b = blockIdx.y;
    int v = (blockIdx.x << 8) + threadIdx.x;
    float val = 0.f;
    if (blockIdx.x < 2) {
        __shared__ float sh[8];
        __shared__ float snorm;
        int t = threadIdx.x;
        float v0 = z[b * 512 + t], v1 = z[b * 512 + 256 + t];
        float s = v0 * v0 + v1 * v1;
        #pragma unroll
        for (int o = 16; o; o >>= 1) s += __shfl_down_sync(~0u, s, o);
        if ((t & 31) == 0) sh[t >> 5] = s;
        __syncthreads();
        if (t < 8) {
            float x = sh[t];
            #pragma unroll
            for (int o = 4; o; o >>= 1) x += __shfl_down_sync(0xffu, x, o);
            if (t == 0) snorm = fmaxf(sqrtf(x), 1e-12f);
        }
        __syncthreads();
        val = z[b * 512 + v] / snorm;
    }
    #pragma unroll
    for (int c = 0; c < NC; c++) g_state[((b * NC + c) << 15) + v] = val;
}

// ---------------- sobel (best-known R5) ----------------

__global__ void __launch_bounds__(512) k_sobel() {
    __shared__ float sl[2][4][36][32];
    __shared__ float red[16][14];
    const int c = blockIdx.x, b = blockIdx.y;
    const int tid = threadIdx.x;
    const int lane = tid & 31, wid = tid >> 5;
    const int h0 = wid * 2;
    const float* __restrict__ xin = g_state + ((size_t)(b * NC + c) << 15);
    float* __restrict__ featb = g_feat + (size_t)(b * CIN + c) * VOL;

    for (int i = tid; i < 1024; i += 512) {
        int w = i & 31, r = (i >> 5) & 3, arr = (i >> 7) & 3, bu = i >> 9;
        int hp = (r < 2) ? r : r + 32;
        sl[bu][arr][hp][w] = 0.f;
    }

    const float R2 = 0.70710678118654752f;
    const float S1 = 1.f + R2;

    float stat[14];
    #pragma unroll
    for (int i = 0; i < 14; i++) stat[i] = 0.f;
    float W[2][6][5];
    #pragma unroll
    for (int r = 0; r < 2; r++)
        #pragma unroll
        for (int a = 0; a < 6; a++)
            #pragma unroll
            for (int k = 0; k < 5; k++) W[r][a][k] = 0.f;

    float xc[2];
    xc[0] = xin[((h0 + 0) << 5) + lane];
    xc[1] = xin[((h0 + 1) << 5) + lane];

    __syncthreads();

    float sw3[2], dw3[2], sw5[2], dw5[2];

    #pragma unroll 2
    for (int s = 0; s < 34; s++) {
        const int bu = s & 1;
        float xn0 = 0.f, xn1 = 0.f;
        if (s + 1 < 32) {
            xn0 = xin[((s + 1) << 10) + ((h0 + 0) << 5) + lane];
            xn1 = xin[((s + 1) << 10) + ((h0 + 1) << 5) + lane];
        }
        if (s < 32) {
            #pragma unroll
            for (int r = 0; r < 2; r++) {
                float xv = xc[r];
                stat[0] += xv; stat[1] += xv * xv;
                float xm1 = __shfl_up_sync(~0u, xv, 1);   if (lane == 0)  xm1 = 0.f;
                float xm2 = __shfl_up_sync(~0u, xv, 2);   if (lane < 2)   xm2 = 0.f;
                float xp1 = __shfl_down_sync(~0u, xv, 1); if (lane == 31) xp1 = 0.f;
                float xp2 = __shfl_down_sync(~0u, xv, 2); if (lane > 29)  xp2 = 0.f;
                sw3[r] = xm1 + 2.f * xv + xp1;
                dw3[r] = xp1 - xm1;
                sw5[r] = xm2 + xp2 + S1 * (xm1 + xp1) + 2.f * xv;
                dw5[r] = (xp2 - xm2) + R2 * (xp1 - xm1);
                int hp = h0 + r + 2;
                sl[bu][0][hp][lane] = sw3[r];
                sl[bu][1][hp][lane] = dw3[r];
                sl[bu][2][hp][lane] = sw5[r];
                sl[bu][3][hp][lane] = dw5[r];
            }
        }
        xc[0] = xn0; xc[1] = xn1;
        __syncthreads();
        #pragma unroll
        for (int r = 0; r < 2; r++) {
            float a30, a31, a32, a50, a51, a52;
            if (s < 32) {
                int hp = h0 + r + 2;
                float s3m = sl[bu][0][hp - 1][lane], s3p = sl[bu][0][hp + 1][lane];
                float d3m = sl[bu][1][hp - 1][lane], d3p = sl[bu][1][hp + 1][lane];
                float s5m2 = sl[bu][2][hp - 2][lane], s5m1 = sl[bu][2][hp - 1][lane];
                float s5p1 = sl[bu][2][hp + 1][lane], s5p2 = sl[bu][2][hp + 2][lane];
                float d5m2 = sl[bu][3][hp - 2][lane], d5m1 = sl[bu][3][hp - 1][lane];
                float d5p1 = sl[bu][3][hp + 1][lane], d5p2 = sl[bu][3][hp + 2][lane];
                a30 = d3m + 2.f * dw3[r] + d3p;
                a31 = s3p - s3m;
                a32 = s3m + 2.f * sw3[r] + s3p;
                a50 = d5m2 + d5p2 + S1 * (d5m1 + d5p1) + 2.f * dw5[r];
                a51 = (s5p2 - s5m2) + R2 * (s5p1 - s5m1);
                a52 = s5m2 + s5p2 + S1 * (s5m1 + s5p1) + 2.f * sw5[r];
            } else {
                a30 = a31 = a32 = a50 = a51 = a52 = 0.f;
            }
            #pragma unroll
            for (int a = 0; a < 6; a++) {
                W[r][a][0] = W[r][a][1]; W[r][a][1] = W[r][a][2];
                W[r][a][2] = W[r][a][3]; W[r][a][3] = W[r][a][4];
            }
            W[r][0][4] = a32; W[r][1][4] = a31; W[r][2][4] = a30;
            W[r][3][4] = a52; W[r][4][4] = a51; W[r][5][4] = a50;

            if (s >= 2) {
                int dc = s - 2;
                float o1 = W[r][0][3] - W[r][0][1];
                float o2 = W[r][1][1] + 2.f * W[r][1][2] + W[r][1][3];
                float o3 = W[r][2][1] + 2.f * W[r][2][2] + W[r][2][3];
                float o4 = (W[r][3][4] - W[r][3][0]) + R2 * (W[r][3][3] - W[r][3][1]);
                float o5 = W[r][4][0] + W[r][4][4] + S1 * (W[r][4][1] + W[r][4][3]) + 2.f * W[r][4][2];
                float o6 = W[r][5][0] + W[r][5][4] + S1 * (W[r][5][1] + W[r][5][3]) + 2.f * W[r][5][2];
                int v = (dc << 10) + ((h0 + r) << 5) + lane;
                featb[(size_t)32 * VOL + v]  = o1;
                featb[(size_t)64 * VOL + v]  = o2;
                featb[(size_t)96 * VOL + v]  = o3;
                featb[(size_t)128 * VOL + v] = o4;
                featb[(size_t)160 * VOL + v] = o5;
                featb[(size_t)192 * VOL + v] = o6;
                stat[2]  += o1; stat[3]  += o1 * o1;
                stat[4]  += o2; stat[5]  += o2 * o2;
                stat[6]  += o3; stat[7]  += o3 * o3;
                stat[8]  += o4; stat[9]  += o4 * o4;
                stat[10] += o5; stat[11] += o5 * o5;
                stat[12] += o6; stat[13] += o6 * o6;
            }
        }
    }

    #pragma unroll
    for (int i = 0; i < 14; i++) {
        float v = stat[i];
        #pragma unroll
        for (int o = 16; o; o >>= 1) v += __shfl_down_sync(~0u, v, o);
        stat[i] = v;
    }
    if (lane == 0)
        #pragma unroll
        for (int i = 0; i < 14; i++) red[wid][i] = stat[i];
    __syncthreads();
    if (tid < 14) {
        double acc = 0.0;
        #pragma unroll
        for (int k = 0; k < 16; k++) acc += (double)red[k][tid];
        int g = tid >> 1;
        if (tid & 1) g_sqd [b * CIN + g * 32 + c] = acc;
        else         g_sumd[b * CIN + g * 32 + c] = acc;
    }
}

// ---------------- fold norm into weights (theta inlined) ----------------

__global__ void k_fold(const int* __restrict__ y, const float* __restrict__ hw,
                       const float* __restrict__ hb) {
    int b = blockIdx.x, tid = threadIdx.x;
    int lane = tid & 31, wid = tid >> 5;
    __shared__ float smean[CIN], srs[CIN];
    if (tid < CIN) {
        double m = g_sumd[b * CIN + tid] * (1.0 / 32768.0);
        double var = g_sqd[b * CIN + tid] * (1.0 / 32768.0) - m * m;
        smean[tid] = (float)m;
        srs[tid] = (float)rsqrt(var + 1e-5);
    }
    __syncthreads();
    const float* th = hw + (size_t)y[b] * KT;   // theta[k] = th[k] + hb[k]
    float* w = g_w + b * KT;
    #pragma unroll
    for (int j = 0; j < 8; j++) {
        int o = wid * 8 + j;
        int off = (o < 32) ? o * 224 : 9312 + (o - 32) * 224;
        float corr = 0.f;
        #pragma unroll
        for (int q = 0; q < 7; q++) {
            int cc = lane + q * 32;
            float wv = (th[off + cc] + hb[off + cc]) * srs[cc];
            w[WC_OFF + cc * 64 + o] = wv;
            corr += wv * smean[cc];
        }
        #pragma unroll
        for (int d = 16; d; d >>= 1) corr += __shfl_down_sync(~0u, corr, d);
        if (lane == 0) {
            float braw = (o < 32) ? (th[7168 + o] + hb[7168 + o])
                                  : (th[16480 + o - 32] + hb[16480 + o - 32]);
            w[B64_OFF + o] = braw - corr;
        }
    }
    for (int i = tid; i < 1024; i += 256) {
        int r = i >> 5, cc = i & 31;
        w[WM_OFF + cc * 32 + r] = th[7200 + r * 32 + cc] + hb[7200 + r * 32 + cc];
        w[WO_OFF + cc * 32 + r] = th[8256 + r * 32 + cc] + hb[8256 + r * 32 + cc];
    }
    if (tid < 32) {
        w[BM_OFF + tid] = th[8224 + tid] + hb[8224 + tid];
        w[BO_OFF + tid] = th[9280 + tid] + hb[9280 + tid];
    }
}

// ---------------- register-blocked residual MLP (best-known R5) ----------
// block: 64 outputs x 128 voxels, 256 threads; thread = 8 out x 4 vox
// 16-channel chunks, 3-buffer cp.async ring, 1 barrier per chunk
#define XS   0       // [3][16][128] = 6144
#define WS   6144    // [3][16][64]  = 3072
#define HSO  0       // [64][132] = 8448 (union over XS/WS after stage 1)
#define SWB  9216    // b64[64] | bm[32] | bo[32] | wm[1024] | wo[1024] = 2176
#define H2S  11392   // [32][129] = 4128
#define SM_FLOATS 15520

__global__ void __launch_bounds__(256) k_residual() {
    extern __shared__ float sm[];
    const int tid = threadIdx.x;
    const int wid = tid >> 5, lane = tid & 31;
    const int b = blockIdx.y;
    const int v0 = blockIdx.x << 7;
    const float* gw = g_w + b * KT;
    unsigned swa = (unsigned)__cvta_generic_to_shared(sm);

    if (tid < 64)  sm[SWB + tid]       = gw[B64_OFF + tid];
    if (tid < 32)  sm[SWB + 64 + tid]  = gw[BM_OFF + tid];
    if (tid >= 32 && tid < 64) sm[SWB + 96 + (tid - 32)] = gw[BO_OFF + tid - 32];
    for (int i = tid; i < 1024; i += 256) sm[SWB + 128 + i]  = gw[WM_OFF + i];
    for (int i = tid; i < 1024; i += 256) sm[SWB + 1152 + i] = gw[WO_OFF + i];

    const int xrow0 = tid >> 5, clw = tid & 31;
    auto issue = [&](int ch) {
        int slot = ch % 3;
        int cc0 = ch * 16 + xrow0;
        const float* xsrc0 = (cc0 < 32)
            ? g_state + ((size_t)(b * NC + cc0) << 15) + v0 + clw * 4
            : g_feat  + ((size_t)(b * CIN + cc0) << 15) + v0 + clw * 4;
        CPA16(swa + (XS + slot * 2048 + xrow0 * 128 + clw * 4) * 4, xsrc0);
        int cc1 = cc0 + 8;
        const float* xsrc1 = (cc1 < 32)
            ? g_state + ((size_t)(b * NC + cc1) << 15) + v0 + clw * 4
            : g_feat  + ((size_t)(b * CIN + cc1) << 15) + v0 + clw * 4;
        CPA16(swa + (XS + slot * 2048 + (xrow0 + 8) * 128 + clw * 4) * 4, xsrc1);
        const float* wsrc = gw + WC_OFF + ch * 1024 + tid * 4;
        CPA16(swa + (WS + slot * 1024 + tid * 4) * 4, wsrc);
    };

    issue(0); CPCOMMIT();
    issue(1); CPCOMMIT();

    unsigned long long acc[16];
    #pragma unroll
    for (int i = 0; i < 16; i++) acc[i] = 0ull;

    for (int ch = 0; ch < 14; ch++) {
        if (ch < 13) CPWAIT(1); else CPWAIT(0);
        __syncthreads();
        if (ch + 2 < 14) { issue(ch + 2); CPCOMMIT(); }
        const float* xb = sm + XS + (ch % 3) * 2048;
        const float* wb = sm + WS + (ch % 3) * 1024;
        #pragma unroll
        for (int kk = 0; kk < 16; kk++) {
            float4 xv = *reinterpret_cast<const float4*>(xb + kk * 128 + lane * 4);
            unsigned long long xq0, xq1, xq2, xq3;
            BCAST(xq0, xv.x); BCAST(xq1, xv.y); BCAST(xq2, xv.z); BCAST(xq3, xv.w);
            const ulonglong2* wp =
                reinterpret_cast<const ulonglong2*>(wb + kk * 64 + wid * 8);
            ulonglong2 wA = wp[0], wB = wp[1];
            FMA2(acc[0],  wA.x, xq0); FMA2(acc[1],  wA.x, xq1);
            FMA2(acc[2],  wA.x, xq2); FMA2(acc[3],  wA.x, xq3);
            FMA2(acc[4],  wA.y, xq0); FMA2(acc[5],  wA.y, xq1);
            FMA2(acc[6],  wA.y, xq2); FMA2(acc[7],  wA.y, xq3);
            FMA2(acc[8],  wB.x, xq0); FMA2(acc[9],  wB.x, xq1);
            FMA2(acc[10], wB.x, xq2); FMA2(acc[11], wB.x, xq3);
            FMA2(acc[12], wB.y, xq0); FMA2(acc[13], wB.y, xq1);
            FMA2(acc[14], wB.y, xq2); FMA2(acc[15], wB.y, xq3);
        }
    }
    __syncthreads();   // ring dead -> HSO region may be written

    #pragma unroll
    for (int j = 0; j < 4; j++) {
        float lo0, hi0, lo1, hi1, lo2, hi2, lo3, hi3;
        UNPK(lo0, hi0, acc[j * 4 + 0]); UNPK(lo1, hi1, acc[j * 4 + 1]);
        UNPK(lo2, hi2, acc[j * 4 + 2]); UNPK(lo3, hi3, acc[j * 4 + 3]);
        int o = wid * 8 + 2 * j;
        *reinterpret_cast<float4*>(sm + HSO + o * 132 + lane * 4)
            = make_float4(lo0, lo1, lo2, lo3);
        *reinterpret_cast<float4*>(sm + HSO + (o + 1) * 132 + lane * 4)
            = make_float4(hi0, hi1, hi2, hi3);
    }
    __syncthreads();

    // ---- stage 2 (per voxel, two 32x32 GEMMs; stage-1 biases added here) ----
    const int v = tid & 127, half = tid >> 7;
    const int obase = half * 16;

    float hv[32];
    #pragma unroll
    for (int jj = 0; jj < 32; jj++) {
        float tv = sm[HSO + jj * 132 + v] + sm[SWB + jj];
        hv[jj] = tv > 0.f ? tv : 0.2f * tv;
    }

    unsigned long long m2[8];
    {
        const unsigned long long* bmp =
            reinterpret_cast<const unsigned long long*>(sm + SWB + 64 + obase);
        #pragma unroll
        for (int p = 0; p < 8; p++) m2[p] = bmp[p];
    }
    #pragma unroll
    for (int jj = 0; jj < 32; jj++) {
        unsigned long long xj; BCAST(xj, hv[jj]);
        const unsigned long long* wr =
            reinterpret_cast<const unsigned long long*>(sm + SWB + 128 + jj * 32 + obase);
        #pragma unroll
        for (int p = 0; p < 8; p++) FMA2(m2[p], wr[p], xj);
    }
    #pragma unroll
    for (int p = 0; p < 8; p++) {
        float lo, hi; UNPK(lo, hi, m2[p]);
        lo = lo > 0.f ? lo : 0.2f * lo;
        hi = hi > 0.f ? hi : 0.2f * hi;
        sm[H2S + (obase + 2 * p) * 129 + v]     = lo;
        sm[H2S + (obase + 2 * p + 1) * 129 + v] = hi;
    }
    __syncthreads();

    unsigned long long f[8];
    {
        const unsigned long long* bop =
            reinterpret_cast<const unsigned long long*>(sm + SWB + 96 + obase);
        #pragma unroll
        for (int p = 0; p < 8; p++) f[p] = bop[p];
    }
    #pragma unroll
    for (int i = 0; i < 32; i++) {
        float h2 = sm[H2S + i * 129 + v];
        unsigned long long xi; BCAST(xi, h2);
        const unsigned long long* wr =
            reinterpret_cast<const unsigned long long*>(sm + SWB + 1152 + i * 32 + obase);
        #pragma unroll
        for (int p = 0; p < 8; p++) FMA2(f[p], wr[p], xi);
    }

    float* st = g_state + ((size_t)(b * NC) << 15) + v0 + v;
    #pragma unroll
    for (int p = 0; p < 8; p++) {
        float t0, t1; UNPK(t0, t1, f[p]);
        int o = obase + 2 * p;
        float s0 = sm[HSO + (32 + o) * 132 + v] + sm[SWB + 32 + o];
        float s1 = sm[HSO + (33 + o) * 132 + v] + sm[SWB + 33 + o];
        st[(size_t)o << 15]       += 0.1f * (t0 + s0);
        st[(size_t)(o + 1) << 15] += 0.1f * (t1 + s1);
    }
}

// ---------------- channel mean ----------------

__global__ void k_final(float* __restrict__ out) {
    int b = blockIdx.y;
    int v = (blockIdx.x << 8) + threadIdx.x;
    const float* st = g_state + b * NC * VOL + v;
    float s = 0.f;
    #pragma unroll
    for (int c = 0; c < NC; c++) s += st[c << 15];
    out[b * VOL + v] = s * (1.f / 32.f);
}

// ---------------- launch ----------------

extern "C" void kernel_launch(void* const* d_in, const int* in_sizes, int n_in,
                              void* d_out, int out_size) {
    const float* z  = (const float*)d_in[0];
    const int*   y  = (const int*)d_in[1];
    const float* hw = (const float*)d_in[2];
    const float* hb = (const float*)d_in[3];
    float* out = (float*)d_out;
    (void)in_sizes; (void)n_in; (void)out_size;

    cudaFuncSetAttribute(k_residual, cudaFuncAttributeMaxDynamicSharedMemorySize,
                         SM_FLOATS * 4);

    k_init<<<dim3(128, 4), 256>>>(z);
    for (int it = 0; it < 4; it++) {
        k_sobel<<<dim3(32, 4), 512>>>();
        k_fold<<<4, 256>>>(y, hw, hb);
        k_residual<<<dim3(256, 4), 256, SM_FLOATS * 4>>>();
    }
    k_final<<<dim3(128, 4), 256>>>(out);
}